// round 15
// baseline (speedup 1.0000x reference)
#include <cuda_runtime.h>
#include <stdint.h>

#define BT 256
#define SLEN 8192
#define HALF 4096
#define NWH 128        // 32-bit mask words per half-row

__device__ float g_sum[4096];
__device__ int   g_cnt[4096];
__device__ int   g_done = 0;

__constant__ float c_tab16[16] = {
    10.0f, 0.16807f, 0.2401f, 0.343f, 0.49f, 0.7f, 0.1f, 1.0f,
    20.0f, 20.0f, 20.0f, 20.0f, 20.0f, 20.0f, 20.0f, 20.0f
};

__device__ __forceinline__ unsigned long long flipDiag8x8(unsigned long long x)
{
    unsigned long long t;
    t = 0x0f0f0f0f00000000ULL & (x ^ (x << 28)); x ^= t ^ (t >> 28);
    t = 0x3333000033330000ULL & (x ^ (x << 14)); x ^= t ^ (t >> 14);
    t = 0x5500550055005500ULL & (x ^ (x <<  7)); x ^= t ^ (t >>  7);
    return x;
}

__device__ __forceinline__ unsigned smem_u32(const void* p)
{
    return (unsigned)__cvta_generic_to_shared(p);
}

__device__ __forceinline__ unsigned dsmem_read(const void* local_p, unsigned rank)
{
    unsigned la = smem_u32(local_p), ra, v;
    asm volatile("mapa.shared::cluster.u32 %0, %1, %2;" : "=r"(ra) : "r"(la), "r"(rank));
    asm volatile("ld.shared::cluster.u32 %0, [%1];" : "=r"(v) : "r"(ra));
    return v;
}

__device__ __forceinline__ void cluster_sync_all()
{
    asm volatile("barrier.cluster.arrive.aligned;" ::: "memory");
    asm volatile("barrier.cluster.wait.aligned;" ::: "memory");
}

__global__ void __launch_bounds__(BT, 6) __cluster_dims__(2, 1, 1)
pal_row_kernel(const float4* __restrict__ logits4, const int* __restrict__ labels,
               float* __restrict__ out, int nblk)
{
    __shared__ float s_ce[NWH * 33];             // half-row CE, 33-stride padded
    __shared__ unsigned s_m[5][NWH + 2];         // valid,l0,l1,hi,podd; pads at [0],[129]
    __shared__ float s_tab[256];
    __shared__ int s_scan[4], s_hasw[4];
    __shared__ int s_xch[2];                     // {total vstate, hasbits} published to peer
    __shared__ int s_rem[2];                     // peer's {total vstate, hasbits}
    __shared__ float s_racc[8];
    __shared__ int s_rcnt[8], s_last;

    const int row = blockIdx.x >> 1;
    const int half = blockIdx.x & 1;
    const unsigned peer = (unsigned)(half ^ 1);
    const int tid = threadIdx.x;
    const int lane = tid & 31;
    const int wid = tid >> 5;

    if (tid < 5) { s_m[tid][0] = 0; s_m[tid][NWH + 1] = 0; }
    {
        int t = tid;
        float v = c_tab16[t & 15];
        v *= ((t >> 5) & 1) ? 3.0f : (((t >> 4) & 1) ? 2.0f : 1.0f);
        if ((t >> 6) & 1) v *= 100.0f;
        if ((t >> 7) & 1) v *= 0.1f;
        s_tab[t] = v;
    }

    const float4* lrow = logits4 + (size_t)row * SLEN + half * HALF;
    const int* labrow = labels + (size_t)row * SLEN + half * HALF;

    // ---- Pass A: 2 elements/thread/iter over this half (4096 elems) ----
#pragma unroll
    for (int k = 0; k < 8; k++) {
        const int i0 = tid + (k << 8);
        const int i1 = i0 + 2048;
        float4 xa = __ldcs(lrow + i0);
        float4 xb = __ldcs(lrow + i1);
        int la = __ldcs(labrow + i0);
        int lb = __ldcs(labrow + i1);

        float am01 = fmaxf(xa.x, xa.y), am23 = fmaxf(xa.z, xa.w);
        float abest = fmaxf(am01, am23);
        bool ahi = am23 > am01;
        bool ab0 = ahi ? (xa.w > xa.z) : (xa.y > xa.x);
        float ae = __expf(xa.x - abest) + __expf(xa.y - abest) +
                   __expf(xa.z - abest) + __expf(xa.w - abest);
        float alse = abest + __logf(ae);
        bool avalid = (la != -100);
        bool al0 = (la & 1) != 0;
        bool al1 = (la & 2) != 0;
        float axl = al1 ? (al0 ? xa.w : xa.z) : (al0 ? xa.y : xa.x);
        float ace = avalid ? (alse - axl) * (al1 ? 30.0f : 1.0f) : 0.0f;
        s_ce[(i0 >> 5) * 33 + (i0 & 31)] = ace;

        float bm01 = fmaxf(xb.x, xb.y), bm23 = fmaxf(xb.z, xb.w);
        float bbest = fmaxf(bm01, bm23);
        bool bhi = bm23 > bm01;
        bool bb0 = bhi ? (xb.w > xb.z) : (xb.y > xb.x);
        float be = __expf(xb.x - bbest) + __expf(xb.y - bbest) +
                   __expf(xb.z - bbest) + __expf(xb.w - bbest);
        float blse = bbest + __logf(be);
        bool bvalid = (lb != -100);
        bool bl0 = (lb & 1) != 0;
        bool bl1 = (lb & 2) != 0;
        float bxl = bl1 ? (bl0 ? xb.w : xb.z) : (bl0 ? xb.y : xb.x);
        float bce = bvalid ? (blse - bxl) * (bl1 ? 30.0f : 1.0f) : 0.0f;
        s_ce[(i1 >> 5) * 33 + (i1 & 31)] = bce;

        unsigned av  = __ballot_sync(0xffffffffu, avalid);
        unsigned aL0 = __ballot_sync(0xffffffffu, al0);
        unsigned aL1 = __ballot_sync(0xffffffffu, al1);
        unsigned aHI = __ballot_sync(0xffffffffu, ahi);
        unsigned aPO = __ballot_sync(0xffffffffu, ab0);
        unsigned bv  = __ballot_sync(0xffffffffu, bvalid);
        unsigned bL0 = __ballot_sync(0xffffffffu, bl0);
        unsigned bL1 = __ballot_sync(0xffffffffu, bl1);
        unsigned bHI = __ballot_sync(0xffffffffu, bhi);
        unsigned bPO = __ballot_sync(0xffffffffu, bb0);
        if (lane == 0) {
            int wa = (k << 3) + wid + 1;
            int wb = wa + 64;
            s_m[0][wa] = av;  s_m[1][wa] = aL0; s_m[2][wa] = aL1;
            s_m[3][wa] = aHI; s_m[4][wa] = aPO;
            s_m[0][wb] = bv;  s_m[1][wb] = bL0; s_m[2][wb] = bL1;
            s_m[3][wb] = bHI; s_m[4][wb] = bPO;
        }
    }
    __syncthreads();

    // ---- warp scans over this half's 128 words (threads 0-127) ----
    int wx = -1;
    unsigned hv = 0, hlo = 0, hl1 = 0, hhi = 0, hpo = 0;
    unsigned t2 = 0, t3 = 0, p2 = 0, p3 = 0;
    if (tid < NWH) {
        const int w = tid;
        hv  = s_m[0][w + 1];
        hlo = s_m[1][w + 1];
        hl1 = s_m[2][w + 1];
        hhi = s_m[3][w + 1];
        hpo = s_m[4][w + 1];
        t2 = hl1 & ~hlo; t3 = hl1 & hlo;
        p2 = hhi & ~hpo; p3 = hhi & hpo;
        const int gw = (half << 7) + w;          // global word index
        int vstate = -1;
        if (hv) {
            int lv = 31 - __clz(hv);
            vstate = (((gw << 5) + lv) << 2) | ((int)((hpo >> lv) & 1u) << 1) | (int)((hlo >> lv) & 1u);
        }
        int inc = vstate;
#pragma unroll
        for (int d = 1; d < 32; d <<= 1) {
            int o = __shfl_up_sync(0xffffffffu, inc, d);
            if (lane >= d) inc = max(inc, o);
        }
        wx = __shfl_up_sync(0xffffffffu, inc, 1);
        if (lane == 0) wx = -1;
        if (lane == 31) s_scan[wid] = inc;
        int hb = (t2 ? 1 : 0) | (t3 ? 2 : 0) | (p2 ? 4 : 0) | (p3 ? 8 : 0);
        hb = __reduce_or_sync(0xffffffffu, hb);
        if (lane == 0) s_hasw[wid] = hb;
    }
    __syncthreads();

    if (tid == 0) {
        int tot = max(max(s_scan[0], s_scan[1]), max(s_scan[2], s_scan[3]));
        int hb = s_hasw[0] | s_hasw[1] | s_hasw[2] | s_hasw[3];
        s_xch[0] = tot; s_xch[1] = hb;
    }

    // ---- cluster exchange: publish, read peer's carry/has/boundary, confirm ----
    cluster_sync_all();
    if (tid < 4) {
        int j = tid + 1;
        if (half == 0) {
            // my next-context = peer's word 0 (their s_m[j][1])
            s_m[j][NWH + 1] = dsmem_read(&s_m[j][1], peer);
        } else {
            // my prev-context = peer's word 127 (their s_m[j][NWH])
            s_m[j][0] = dsmem_read(&s_m[j][NWH], peer);
        }
    } else if (tid == 4) {
        s_rem[0] = (int)dsmem_read(&s_xch[0], peer);
    } else if (tid == 5) {
        s_rem[1] = (int)dsmem_read(&s_xch[1], peer);
    }
    cluster_sync_all();

    // ---- plane phase + fused MAC (threads 0-127) ----
    float acc = 0.0f; int cnt = 0;
    if (tid < NWH) {
        const int w = tid;
        int wpre = -1;
        int hs = s_hasw[0] | s_hasw[1] | s_hasw[2] | s_hasw[3] | s_rem[1];
#pragma unroll
        for (int ww = 0; ww < 4; ww++) {
            int t = s_scan[ww];
            if (ww < wid) wpre = max(wpre, t);
        }
        if (half == 1) wpre = max(wpre, s_rem[0]);
        const int pstate = max(wx, wpre);

        // (a) mode-state sample-and-hold -> q6/q7
        unsigned q6, q7;
        {
            int pm_in = 0, tm_in = 0;
            if (pstate >= 0) { pm_in = (pstate >> 1) & 1; tm_in = pstate & 1; }
            unsigned long long P0 = ((unsigned long long)hv << 1) | 1ULL;
            unsigned long long P = P0;
            unsigned long long V = ((unsigned long long)(hpo & hv) << 1) | (unsigned long long)pm_in;
            V |= (V << 1) & ~P;  P |= P << 1;
            V |= (V << 2) & ~P;  P |= P << 2;
            V |= (V << 4) & ~P;  P |= P << 4;
            V |= (V << 8) & ~P;  P |= P << 8;
            V |= (V << 16) & ~P; P |= P << 16;
            V |= (V << 32) & ~P;
            unsigned U = (unsigned)V;
            P = P0;
            V = ((unsigned long long)(hlo & hv) << 1) | (unsigned long long)tm_in;
            V |= (V << 1) & ~P;  P |= P << 1;
            V |= (V << 2) & ~P;  P |= P << 2;
            V |= (V << 4) & ~P;  P |= P << 4;
            V |= (V << 8) & ~P;  P |= P << 8;
            V |= (V << 16) & ~P; P |= P << 16;
            V |= (V << 32) & ~P;
            unsigned Ut = (unsigned)V;
            q6 = ((p2 & ~U) | (p3 & U)) & hv;              // BAD  x100
            q7 = ((t2 & Ut & p2) | (t3 & ~Ut & p3)) & hv;  // GOOD x0.1
        }

        // (b) radius-5 coverage of pred masks -> q4/q5
        unsigned q4, q5;
        {
            unsigned hip = s_m[3][w], hin = s_m[3][w + 2];
            unsigned pop = s_m[4][w], pon = s_m[4][w + 2];
            unsigned p2p = hip & ~pop, p2n = hin & ~pon;
            unsigned p3p = hip & pop,  p3n = hin & pon;
            unsigned long long C2 = ((unsigned long long)(p2p >> 27)) |
                                    ((unsigned long long)p2 << 5) |
                                    ((unsigned long long)p2n << 37);
            unsigned long long C3 = ((unsigned long long)(p3p >> 27)) |
                                    ((unsigned long long)p3 << 5) |
                                    ((unsigned long long)p3n << 37);
            C2 |= (C2 << 1) | (C2 >> 1);  C2 |= (C2 << 2) | (C2 >> 2);  C2 |= (C2 << 2) | (C2 >> 2);
            C3 |= (C3 << 1) | (C3 >> 1);  C3 |= (C3 << 2) | (C3 >> 2);  C3 |= (C3 << 2) | (C3 >> 2);
            unsigned cv2 = (unsigned)(C2 >> 5), cv3 = (unsigned)(C3 >> 5);
            q4 = ((hs & 4) ? (t2 & ~cv2) : 0u) | ((hs & 8) ? (t3 & ~cv3) : 0u); // x2
            q5 = ((hs & 4) ? 0u : t2) | ((hs & 8) ? 0u : t3);                    // x3
        }

        // (c) distance levels -> q0..q3
        unsigned q0, q1, q2, q3;
        {
            unsigned l0p = s_m[1][w], l0n = s_m[1][w + 2];
            unsigned l1p = s_m[2][w], l1n = s_m[2][w + 2];
            unsigned t2p = l1p & ~l0p, t2n = l1n & ~l0n;
            unsigned t3p = l1p & l0p,  t3n = l1n & l0n;
            unsigned long long A2 = ((unsigned long long)(t2p >> 27)) |
                                    ((unsigned long long)t2 << 5) |
                                    ((unsigned long long)t2n << 37);
            unsigned long long A3 = ((unsigned long long)(t3p >> 27)) |
                                    ((unsigned long long)t3 << 5) |
                                    ((unsigned long long)t3n << 37);
            unsigned L0 = ((unsigned)(A2 >> 5) & p2) | ((unsigned)(A3 >> 5) & p3);
            A2 |= (A2 << 1) | (A2 >> 1);  A3 |= (A3 << 1) | (A3 >> 1);
            unsigned L1 = ((unsigned)(A2 >> 5) & p2) | ((unsigned)(A3 >> 5) & p3);
            A2 |= (A2 << 1) | (A2 >> 1);  A3 |= (A3 << 1) | (A3 >> 1);
            unsigned L2 = ((unsigned)(A2 >> 5) & p2) | ((unsigned)(A3 >> 5) & p3);
            A2 |= (A2 << 1) | (A2 >> 1);  A3 |= (A3 << 1) | (A3 >> 1);
            unsigned L3 = ((unsigned)(A2 >> 5) & p2) | ((unsigned)(A3 >> 5) & p3);
            A2 |= (A2 << 1) | (A2 >> 1);  A3 |= (A3 << 1) | (A3 >> 1);
            unsigned L4 = ((unsigned)(A2 >> 5) & p2) | ((unsigned)(A3 >> 5) & p3);
            A2 |= (A2 << 1) | (A2 >> 1);  A3 |= (A3 << 1) | (A3 >> 1);
            unsigned L5 = ((unsigned)(A2 >> 5) & p2) | ((unsigned)(A3 >> 5) & p3);

            unsigned x0 = L0 ^ L1 ^ L2;
            unsigned y0 = (L0 & L1) | (L2 & (L0 | L1));
            unsigned x1 = L3 ^ L4 ^ L5;
            unsigned y1 = (L3 & L4) | (L5 & (L3 | L4));
            unsigned pb0 = x0 ^ x1;
            unsigned cc = x0 & x1;
            unsigned pb1 = y0 ^ y1 ^ cc;
            unsigned pb2 = (y0 & y1) | (cc & (y0 | y1));
            unsigned sel = p2 | p3;
            q0 = pb0 | ~sel;
            q1 = pb1 | ~sel;
            q2 = pb2 | ~sel;
            q3 = ((hs & 1) ? 0u : p2) | ((hs & 2) ? 0u : p3);
        }

        // fused MAC: transpose 8 planes -> idx bytes, gather table, FMA
        const float* cep = s_ce + w * 33;
#pragma unroll
        for (int g = 0; g < 4; g++) {
            unsigned s01 = (unsigned)(g | ((g + 4) << 4));
            unsigned A01 = __byte_perm(q0, q1, s01);
            unsigned A23 = __byte_perm(q2, q3, s01);
            unsigned Aw = __byte_perm(A01, A23, 0x5410);
            unsigned B01 = __byte_perm(q4, q5, s01);
            unsigned B23 = __byte_perm(q6, q7, s01);
            unsigned Bw = __byte_perm(B01, B23, 0x5410);
            unsigned long long tg = flipDiag8x8((unsigned long long)Aw | ((unsigned long long)Bw << 32));
            unsigned lo = (unsigned)tg, hi32 = (unsigned)(tg >> 32);
#pragma unroll
            for (int b = 0; b < 4; b++)
                acc += cep[g * 8 + b] * s_tab[(lo >> (8 * b)) & 0xffu];
#pragma unroll
            for (int b = 0; b < 4; b++)
                acc += cep[g * 8 + 4 + b] * s_tab[(hi32 >> (8 * b)) & 0xffu];
        }
        cnt = __popc(hv);
    }

    // ---- deterministic block reduce (all 256 threads; upper half contributes 0) ----
#pragma unroll
    for (int d = 16; d > 0; d >>= 1) {
        acc += __shfl_down_sync(0xffffffffu, acc, d);
        cnt += __shfl_down_sync(0xffffffffu, cnt, d);
    }
    if (lane == 0) { s_racc[wid] = acc; s_rcnt[wid] = cnt; }
    __syncthreads();
    if (wid == 0) {
        float a = (lane < 8) ? s_racc[lane] : 0.0f;
        int c = (lane < 8) ? s_rcnt[lane] : 0;
#pragma unroll
        for (int d = 4; d > 0; d >>= 1) {
            a += __shfl_down_sync(0xffffffffu, a, d);
            c += __shfl_down_sync(0xffffffffu, c, d);
        }
        if (lane == 0) {
            g_sum[blockIdx.x] = a; g_cnt[blockIdx.x] = c;
            __threadfence();
            int old = atomicAdd(&g_done, 1);
            s_last = (old == (int)gridDim.x - 1) ? 1 : 0;
        }
    }
    __syncthreads();

    // ---- last block: fixed-order final reduce (resets g_done for graph replay) ----
    if (s_last) {
        float a = 0.0f; int c = 0;
        for (int i = tid; i < nblk; i += BT) {
            a += __ldcg(&g_sum[i]);
            c += __ldcg(&g_cnt[i]);
        }
#pragma unroll
        for (int d = 16; d > 0; d >>= 1) {
            a += __shfl_down_sync(0xffffffffu, a, d);
            c += __shfl_down_sync(0xffffffffu, c, d);
        }
        if (lane == 0) { s_racc[wid] = a; s_rcnt[wid] = c; }
        __syncthreads();
        if (wid == 0) {
            a = (lane < 8) ? s_racc[lane] : 0.0f;
            c = (lane < 8) ? s_rcnt[lane] : 0;
#pragma unroll
            for (int d = 4; d > 0; d >>= 1) {
                a += __shfl_down_sync(0xffffffffu, a, d);
                c += __shfl_down_sync(0xffffffffu, c, d);
            }
            if (lane == 0) {
                out[0] = a / fmaxf((float)c, 1.0f);
                g_done = 0;
            }
        }
    }
}

extern "C" void kernel_launch(void* const* d_in, const int* in_sizes, int n_in,
                              void* d_out, int out_size)
{
    const float4* logits = (const float4*)d_in[0];
    const int* labels = (const int*)d_in[1];
    int B = in_sizes[1] / SLEN;
    int nblk = 2 * B;
    pal_row_kernel<<<nblk, BT>>>(logits, labels, (float*)d_out, nblk);
}

// round 17
// speedup vs baseline: 1.1033x; 1.1033x over previous
#include <cuda_runtime.h>
#include <stdint.h>

#define BT 256
#define SLEN 8192
#define NW 8           // warps per block
#define NWORD 256      // 32-bit mask words per row

__device__ float g_sum[4096];
__device__ int   g_cnt[4096];
__device__ int   g_done = 0;

// idx low 4 bits: levelcount (0..6) or 7=neutral, +8 = noTrue
// levelcount = 6-d: d==0 -> 0.1, d=1..5 -> 0.7^d, d>5 -> 10, noTrue -> 20
__constant__ float c_tab16[16] = {
    10.0f, 0.16807f, 0.2401f, 0.343f, 0.49f, 0.7f, 0.1f, 1.0f,
    20.0f, 20.0f, 20.0f, 20.0f, 20.0f, 20.0f, 20.0f, 20.0f
};

__device__ __forceinline__ unsigned long long flipDiag8x8(unsigned long long x)
{
    unsigned long long t;
    t = 0x0f0f0f0f00000000ULL & (x ^ (x << 28)); x ^= t ^ (t >> 28);
    t = 0x3333000033330000ULL & (x ^ (x << 14)); x ^= t ^ (t >> 14);
    t = 0x5500550055005500ULL & (x ^ (x <<  7)); x ^= t ^ (t >>  7);
    return x;
}

__global__ void __launch_bounds__(BT, 4)
pal_row_kernel(const float4* __restrict__ logits4, const int* __restrict__ labels,
               float* __restrict__ out, int B)
{
    __shared__ float s_ce[NWORD * 33];           // 33-stride padded: conflict-free both phases
    __shared__ unsigned s_m[5][NWORD + 2];       // valid,l0,l1,hi,podd; zero pads at [0],[257]
    __shared__ float s_tab[256];
    __shared__ int s_scan[NW], s_hasw[NW];
    __shared__ float s_racc[NW];
    __shared__ int s_rcnt[NW], s_last;

    const int row = blockIdx.x;
    const int tid = threadIdx.x;
    const int lane = tid & 31;
    const int wid = tid >> 5;

    if (tid < 5) { s_m[tid][0] = 0; s_m[tid][NWORD + 1] = 0; }
    // all 256 threads build the 256-entry product table
    {
        int t = tid;
        float v = c_tab16[t & 15];
        v *= ((t >> 5) & 1) ? 3.0f : (((t >> 4) & 1) ? 2.0f : 1.0f);
        if ((t >> 6) & 1) v *= 100.0f;
        if ((t >> 7) & 1) v *= 0.1f;
        s_tab[t] = v;
    }

    const float4* lrow = logits4 + (size_t)row * SLEN;
    const int* labrow = labels + (size_t)row * SLEN;

    // ---- Pass A: software-pipelined (prefetch distance 1); 5 ballots/32 elems ----
    float4 xa = __ldcs(lrow + tid);
    float4 xb = __ldcs(lrow + tid + 4096);
    int la = __ldcs(labrow + tid);
    int lb = __ldcs(labrow + tid + 4096);
#pragma unroll
    for (int k = 0; k < 16; k++) {
        // prefetch next iteration's data BEFORE this iteration's dependency chain
        float4 xa_n, xb_n; int la_n = 0, lb_n = 0;
        if (k < 15) {
            const int j0 = tid + ((k + 1) << 8);
            xa_n = __ldcs(lrow + j0);
            xb_n = __ldcs(lrow + j0 + 4096);
            la_n = __ldcs(labrow + j0);
            lb_n = __ldcs(labrow + j0 + 4096);
        }

        const int i0 = tid + (k << 8);
        const int i1 = i0 + 4096;

        // element a
        float am01 = fmaxf(xa.x, xa.y), am23 = fmaxf(xa.z, xa.w);
        float abest = fmaxf(am01, am23);
        bool ahi = am23 > am01;
        bool ab0 = ahi ? (xa.w > xa.z) : (xa.y > xa.x);
        float ae = __expf(xa.x - abest) + __expf(xa.y - abest) +
                   __expf(xa.z - abest) + __expf(xa.w - abest);
        float alse = abest + __logf(ae);
        bool avalid = (la != -100);
        bool al0 = (la & 1) != 0;
        bool al1 = (la & 2) != 0;
        float axl = al1 ? (al0 ? xa.w : xa.z) : (al0 ? xa.y : xa.x);
        float ace = avalid ? (alse - axl) * (al1 ? 30.0f : 1.0f) : 0.0f;
        s_ce[(i0 >> 5) * 33 + (i0 & 31)] = ace;

        // element b
        float bm01 = fmaxf(xb.x, xb.y), bm23 = fmaxf(xb.z, xb.w);
        float bbest = fmaxf(bm01, bm23);
        bool bhi = bm23 > bm01;
        bool bb0 = bhi ? (xb.w > xb.z) : (xb.y > xb.x);
        float be = __expf(xb.x - bbest) + __expf(xb.y - bbest) +
                   __expf(xb.z - bbest) + __expf(xb.w - bbest);
        float blse = bbest + __logf(be);
        bool bvalid = (lb != -100);
        bool bl0 = (lb & 1) != 0;
        bool bl1 = (lb & 2) != 0;
        float bxl = bl1 ? (bl0 ? xb.w : xb.z) : (bl0 ? xb.y : xb.x);
        float bce = bvalid ? (blse - bxl) * (bl1 ? 30.0f : 1.0f) : 0.0f;
        s_ce[(i1 >> 5) * 33 + (i1 & 31)] = bce;

        unsigned av  = __ballot_sync(0xffffffffu, avalid);
        unsigned aL0 = __ballot_sync(0xffffffffu, al0);
        unsigned aL1 = __ballot_sync(0xffffffffu, al1);
        unsigned aHI = __ballot_sync(0xffffffffu, ahi);
        unsigned aPO = __ballot_sync(0xffffffffu, ab0);
        unsigned bv  = __ballot_sync(0xffffffffu, bvalid);
        unsigned bL0 = __ballot_sync(0xffffffffu, bl0);
        unsigned bL1 = __ballot_sync(0xffffffffu, bl1);
        unsigned bHI = __ballot_sync(0xffffffffu, bhi);
        unsigned bPO = __ballot_sync(0xffffffffu, bb0);
        if (lane == 0) {
            int wa = (k << 3) + wid + 1;
            int wb = wa + 128;
            s_m[0][wa] = av;  s_m[1][wa] = aL0; s_m[2][wa] = aL1;
            s_m[3][wa] = aHI; s_m[4][wa] = aPO;
            s_m[0][wb] = bv;  s_m[1][wb] = bL0; s_m[2][wb] = bL1;
            s_m[3][wb] = bHI; s_m[4][wb] = bPO;
        }

        if (k < 15) { xa = xa_n; xb = xb_n; la = la_n; lb = lb_n; }
    }
    __syncthreads();

    // ---- each thread owns word w = tid ----
    const int w = tid;
    unsigned hv  = s_m[0][w + 1];
    unsigned hlo = s_m[1][w + 1];
    unsigned hl1 = s_m[2][w + 1];
    unsigned hhi = s_m[3][w + 1];
    unsigned hpo = s_m[4][w + 1];
    unsigned t2 = hl1 & ~hlo, t3 = hl1 & hlo;
    unsigned p2 = hhi & ~hpo, p3 = hhi & hpo;
    {
        // scan seed: last valid position's (pred_mode, true_mode)
        int vstate = -1;
        if (hv) {
            int lv = 31 - __clz(hv);
            vstate = (((w << 5) + lv) << 2) | ((int)((hpo >> lv) & 1u) << 1) | (int)((hlo >> lv) & 1u);
        }
        int inc = vstate;
#pragma unroll
        for (int d = 1; d < 32; d <<= 1) {
            int o = __shfl_up_sync(0xffffffffu, inc, d);
            if (lane >= d) inc = max(inc, o);
        }
        int wx = __shfl_up_sync(0xffffffffu, inc, 1);
        if (lane == 0) wx = -1;
        if (lane == 31) s_scan[wid] = inc;
        int hb = (t2 ? 1 : 0) | (t3 ? 2 : 0) | (p2 ? 4 : 0) | (p3 ? 8 : 0);
        hb = __reduce_or_sync(0xffffffffu, hb);
        if (lane == 0) s_hasw[wid] = hb;
        __syncthreads();

        // all threads combine the 8 warp totals serially (8 entries)
        int wpre = -1, hs = 0;
#pragma unroll
        for (int ww = 0; ww < NW; ww++) {
            int t = s_scan[ww];
            if (ww < wid) wpre = max(wpre, t);
            hs |= s_hasw[ww];
        }
        const int pstate = max(wx, wpre);

        // ---- sub-phase (a): mode-state sample-and-hold -> q6/q7 ----
        unsigned q6, q7;
        {
            int pm_in = 0, tm_in = 0;
            if (pstate >= 0) { pm_in = (pstate >> 1) & 1; tm_in = pstate & 1; }
            unsigned long long P0 = ((unsigned long long)hv << 1) | 1ULL;
            unsigned long long P = P0;
            unsigned long long V = ((unsigned long long)(hpo & hv) << 1) | (unsigned long long)pm_in;
            V |= (V << 1) & ~P;  P |= P << 1;
            V |= (V << 2) & ~P;  P |= P << 2;
            V |= (V << 4) & ~P;  P |= P << 4;
            V |= (V << 8) & ~P;  P |= P << 8;
            V |= (V << 16) & ~P; P |= P << 16;
            V |= (V << 32) & ~P;
            unsigned U = (unsigned)V;                 // pred_mode before element e
            P = P0;
            V = ((unsigned long long)(hlo & hv) << 1) | (unsigned long long)tm_in;
            V |= (V << 1) & ~P;  P |= P << 1;
            V |= (V << 2) & ~P;  P |= P << 2;
            V |= (V << 4) & ~P;  P |= P << 4;
            V |= (V << 8) & ~P;  P |= P << 8;
            V |= (V << 16) & ~P; P |= P << 16;
            V |= (V << 32) & ~P;
            unsigned Ut = (unsigned)V;                // true_mode before element e
            q6 = ((p2 & ~U) | (p3 & U)) & hv;                 // BAD  x100
            q7 = ((t2 & Ut & p2) | (t3 & ~Ut & p3)) & hv;     // GOOD x0.1
        }

        // ---- sub-phase (b): radius-5 coverage of pred masks -> q4/q5 ----
        unsigned q4, q5;
        {
            unsigned hip = s_m[3][w], hin = s_m[3][w + 2];
            unsigned pop = s_m[4][w], pon = s_m[4][w + 2];
            unsigned p2p = hip & ~pop, p2n = hin & ~pon;
            unsigned p3p = hip & pop,  p3n = hin & pon;
            unsigned long long C2 = ((unsigned long long)(p2p >> 27)) |
                                    ((unsigned long long)p2 << 5) |
                                    ((unsigned long long)p2n << 37);
            unsigned long long C3 = ((unsigned long long)(p3p >> 27)) |
                                    ((unsigned long long)p3 << 5) |
                                    ((unsigned long long)p3n << 37);
            C2 |= (C2 << 1) | (C2 >> 1);  C2 |= (C2 << 2) | (C2 >> 2);  C2 |= (C2 << 2) | (C2 >> 2);
            C3 |= (C3 << 1) | (C3 >> 1);  C3 |= (C3 << 2) | (C3 >> 2);  C3 |= (C3 << 2) | (C3 >> 2);
            unsigned cv2 = (unsigned)(C2 >> 5), cv3 = (unsigned)(C3 >> 5);
            q4 = ((hs & 4) ? (t2 & ~cv2) : 0u) | ((hs & 8) ? (t3 & ~cv3) : 0u); // x2
            q5 = ((hs & 4) ? 0u : t2) | ((hs & 8) ? 0u : t3);                    // x3
        }

        // ---- sub-phase (c): distance levels -> q0..q3 ----
        unsigned q0, q1, q2, q3;
        {
            unsigned l0p = s_m[1][w], l0n = s_m[1][w + 2];
            unsigned l1p = s_m[2][w], l1n = s_m[2][w + 2];
            unsigned t2p = l1p & ~l0p, t2n = l1n & ~l0n;
            unsigned t3p = l1p & l0p,  t3n = l1n & l0n;
            unsigned long long A2 = ((unsigned long long)(t2p >> 27)) |
                                    ((unsigned long long)t2 << 5) |
                                    ((unsigned long long)t2n << 37);
            unsigned long long A3 = ((unsigned long long)(t3p >> 27)) |
                                    ((unsigned long long)t3 << 5) |
                                    ((unsigned long long)t3n << 37);
            unsigned L0 = ((unsigned)(A2 >> 5) & p2) | ((unsigned)(A3 >> 5) & p3);
            A2 |= (A2 << 1) | (A2 >> 1);  A3 |= (A3 << 1) | (A3 >> 1);
            unsigned L1 = ((unsigned)(A2 >> 5) & p2) | ((unsigned)(A3 >> 5) & p3);
            A2 |= (A2 << 1) | (A2 >> 1);  A3 |= (A3 << 1) | (A3 >> 1);
            unsigned L2 = ((unsigned)(A2 >> 5) & p2) | ((unsigned)(A3 >> 5) & p3);
            A2 |= (A2 << 1) | (A2 >> 1);  A3 |= (A3 << 1) | (A3 >> 1);
            unsigned L3 = ((unsigned)(A2 >> 5) & p2) | ((unsigned)(A3 >> 5) & p3);
            A2 |= (A2 << 1) | (A2 >> 1);  A3 |= (A3 << 1) | (A3 >> 1);
            unsigned L4 = ((unsigned)(A2 >> 5) & p2) | ((unsigned)(A3 >> 5) & p3);
            A2 |= (A2 << 1) | (A2 >> 1);  A3 |= (A3 << 1) | (A3 >> 1);
            unsigned L5 = ((unsigned)(A2 >> 5) & p2) | ((unsigned)(A3 >> 5) & p3);

            // bit-sliced sum of 6 level planes -> 3-bit count
            unsigned x0 = L0 ^ L1 ^ L2;
            unsigned y0 = (L0 & L1) | (L2 & (L0 | L1));
            unsigned x1 = L3 ^ L4 ^ L5;
            unsigned y1 = (L3 & L4) | (L5 & (L3 | L4));
            unsigned pb0 = x0 ^ x1;
            unsigned cc = x0 & x1;
            unsigned pb1 = y0 ^ y1 ^ cc;
            unsigned pb2 = (y0 & y1) | (cc & (y0 | y1));
            unsigned sel = p2 | p3;
            q0 = pb0 | ~sel;
            q1 = pb1 | ~sel;
            q2 = pb2 | ~sel;
            q3 = ((hs & 1) ? 0u : p2) | ((hs & 2) ? 0u : p3);
        }

        // fused MAC: transpose 8 planes -> idx bytes in regs, gather table, FMA
        float acc = 0.0f;
        const float* cep = s_ce + w * 33;
#pragma unroll
        for (int g = 0; g < 4; g++) {
            unsigned s01 = (unsigned)(g | ((g + 4) << 4));
            unsigned A01 = __byte_perm(q0, q1, s01);
            unsigned A23 = __byte_perm(q2, q3, s01);
            unsigned Aw = __byte_perm(A01, A23, 0x5410);
            unsigned B01 = __byte_perm(q4, q5, s01);
            unsigned B23 = __byte_perm(q6, q7, s01);
            unsigned Bw = __byte_perm(B01, B23, 0x5410);
            unsigned long long tg = flipDiag8x8((unsigned long long)Aw | ((unsigned long long)Bw << 32));
            unsigned lo = (unsigned)tg, hi32 = (unsigned)(tg >> 32);
#pragma unroll
            for (int b = 0; b < 4; b++)
                acc += cep[g * 8 + b] * s_tab[(lo >> (8 * b)) & 0xffu];
#pragma unroll
            for (int b = 0; b < 4; b++)
                acc += cep[g * 8 + 4 + b] * s_tab[(hi32 >> (8 * b)) & 0xffu];
        }
        int cnt = __popc(hv);

        // ---- deterministic block reduce ----
#pragma unroll
        for (int d = 16; d > 0; d >>= 1) {
            acc += __shfl_down_sync(0xffffffffu, acc, d);
            cnt += __shfl_down_sync(0xffffffffu, cnt, d);
        }
        if (lane == 0) { s_racc[wid] = acc; s_rcnt[wid] = cnt; }
    }
    __syncthreads();
    if (wid == 0) {
        float a = (lane < NW) ? s_racc[lane] : 0.0f;
        int c = (lane < NW) ? s_rcnt[lane] : 0;
#pragma unroll
        for (int d = 4; d > 0; d >>= 1) {
            a += __shfl_down_sync(0xffffffffu, a, d);
            c += __shfl_down_sync(0xffffffffu, c, d);
        }
        if (lane == 0) {
            g_sum[row] = a; g_cnt[row] = c;
            __threadfence();
            int old = atomicAdd(&g_done, 1);
            s_last = (old == (int)gridDim.x - 1) ? 1 : 0;
        }
    }
    __syncthreads();

    // ---- last block: fixed-order final reduce (resets g_done for graph replay) ----
    if (s_last) {
        float a = 0.0f; int c = 0;
        for (int i = tid; i < B; i += BT) {
            a += __ldcg(&g_sum[i]);
            c += __ldcg(&g_cnt[i]);
        }
#pragma unroll
        for (int d = 16; d > 0; d >>= 1) {
            a += __shfl_down_sync(0xffffffffu, a, d);
            c += __shfl_down_sync(0xffffffffu, c, d);
        }
        if (lane == 0) { s_racc[wid] = a; s_rcnt[wid] = c; }
        __syncthreads();
        if (wid == 0) {
            a = (lane < NW) ? s_racc[lane] : 0.0f;
            c = (lane < NW) ? s_rcnt[lane] : 0;
#pragma unroll
            for (int d = 4; d > 0; d >>= 1) {
                a += __shfl_down_sync(0xffffffffu, a, d);
                c += __shfl_down_sync(0xffffffffu, c, d);
            }
            if (lane == 0) {
                out[0] = a / fmaxf((float)c, 1.0f);
                g_done = 0;
            }
        }
    }
}

extern "C" void kernel_launch(void* const* d_in, const int* in_sizes, int n_in,
                              void* d_out, int out_size)
{
    const float4* logits = (const float4*)d_in[0];
    const int* labels = (const int*)d_in[1];
    int B = in_sizes[1] / SLEN;
    pal_row_kernel<<<B, BT>>>(logits, labels, (float*)d_out, B);
}